// round 13
// baseline (speedup 1.0000x reference)
#include <cuda_runtime.h>
#include <cuda_bf16.h>
#include <cstdint>

#define D 128
#define MAXE 1000000
#define MAXN 100000

typedef unsigned long long u64;

// ================= scratch =================
__device__ int      g_src[MAXE];
__device__ int      g_dst[MAXE];
__device__ int      g_csr[MAXE];
__device__ int      g_cnt[MAXN];        // zero-init; re-zeroed inline in k_scanfill
__device__ int      g_off[MAXN + 1];
__device__ int      g_cursor[MAXN];
__device__ volatile int g_scanflag[128];// reset by k_prep at replay start
__device__ int      g_barA;             // arrive counter (reset by k_prep)
__device__ volatile int g_barR;         // release flag   (reset by k_prep)
__device__ float    g_h1[(size_t)MAXN * D];
__device__ uint32_t g_Xp[(size_t)MAXN * D];
__device__ uint32_t g_X2p[(size_t)MAXN * D];
__device__ uint32_t g_Gp[(size_t)MAXN * D];
__device__ __nv_bfloat16 g_B1hi[128 * 256];
__device__ __nv_bfloat16 g_B1lo[128 * 256];
__device__ __nv_bfloat16 g_B2hi[128 * 256];
__device__ __nv_bfloat16 g_B2lo[128 * 256];

// ================= packing helpers =================
__device__ __forceinline__ uint32_t packv(float v) {
    unsigned short h = __bfloat16_as_ushort(__float2bfloat16(v));
    float r = v - __uint_as_float((uint32_t)h << 16);
    unsigned short l = __bfloat16_as_ushort(__float2bfloat16(r));
    return (uint32_t)h | ((uint32_t)l << 16);
}
__device__ __forceinline__ void split_bf(float v, __nv_bfloat16& hi, __nv_bfloat16& lo) {
    hi = __float2bfloat16(v);
    lo = __float2bfloat16(v - __bfloat162float(hi));
}

// ========== launch #1: prep = weight conv + feature pack + edge convert/count + resets ====
__global__ void k_prep(const float* __restrict__ ne,
                       const float* __restrict__ w1l, const float* __restrict__ w1r,
                       const float* __restrict__ w2l, const float* __restrict__ w2r,
                       const int* __restrict__ edge, int N, int E, int convx_blocks) {
    int b = blockIdx.x, tid = threadIdx.x;
    if (b == 0) {                       // reset sync state for this replay's scanfill
        if (tid < 128) g_scanflag[tid] = 0;
        if (tid == 128) g_barA = 0;
        if (tid == 129) g_barR = 0;
    }
    if (b < 128) {
        int layer = b >> 6;
        int t = (b & 63) * 256 + tid;
        int k = t >> 7, n = t & 127;
        const float* Wl = layer ? w2l : w1l;
        const float* Wr = layer ? w2r : w1r;
        __nv_bfloat16* Bhi = layer ? g_B2hi : g_B1hi;
        __nv_bfloat16* Blo = layer ? g_B2lo : g_B1lo;
        __nv_bfloat16 h, l;
        split_bf(Wl[k * 128 + n], h, l);
        Bhi[n * 256 + k] = h; Blo[n * 256 + k] = l;
        split_bf(Wr[k * 128 + n], h, l);
        Bhi[n * 256 + 128 + k] = h; Blo[n * 256 + 128 + k] = l;
    } else if (b < 128 + convx_blocks) {
        size_t i = ((size_t)(b - 128) * 256 + tid) * 4;
        if (i < (size_t)N * D) {
            float4 v = *reinterpret_cast<const float4*>(ne + i);
            *reinterpret_cast<uint4*>(g_Xp + i) =
                make_uint4(packv(v.x), packv(v.y), packv(v.z), packv(v.w));
        }
    } else {
        int i = (b - 128 - convx_blocks) * 256 + tid;
        if (i >= E) return;
        // sampled dtype detection: int64 values < 2^31 have zero odd words
        uint32_t odd = (uint32_t)edge[1] | (uint32_t)edge[3] | (uint32_t)edge[5] |
                       (uint32_t)edge[7] | (uint32_t)edge[9] | (uint32_t)edge[11] |
                       (uint32_t)edge[13] | (uint32_t)edge[15];
        int s, d;
        if (odd == 0) { s = edge[2 * i]; d = edge[2 * E + 2 * i]; }   // int64
        else          { s = edge[i];     d = edge[E + i]; }           // int32
        g_src[i] = s; g_dst[i] = d;
        atomicAdd(&g_cnt[d], 1);
    }
}

// ========== launch #2: scan (decoupled lookback) + resident grid barrier + CSR fill ======
#define SCAN_BLOCK 1024
__global__ void k_scanfill(int N, int E, int nblk) {
    __shared__ int sh[SCAN_BLOCK];
    __shared__ int base;
    int b = blockIdx.x, tid = threadIdx.x;
    int i = b * SCAN_BLOCK + tid;
    int v = (i < N) ? g_cnt[i] : 0;
    if (i < N) g_cnt[i] = 0;                      // reset for next replay
    sh[tid] = v;
    __syncthreads();
#pragma unroll
    for (int s = 1; s < SCAN_BLOCK; s <<= 1) {
        int t = (tid >= s) ? sh[tid - s] : 0;
        __syncthreads();
        sh[tid] += t;
        __syncthreads();
    }
    if (tid == SCAN_BLOCK - 1) {
        __threadfence();
        g_scanflag[b] = sh[SCAN_BLOCK - 1] + 1;   // publish aggregate (+1 = ready)
    }
    if (tid == 0) {
        int run = 0;
        for (int bb = 0; bb < b; bb++) {
            int f;
            while ((f = g_scanflag[bb]) == 0) __nanosleep(40);
            run += f - 1;
        }
        base = run;
        if (b == nblk - 1) g_off[N] = E;
    }
    __syncthreads();
    if (i < N) {
        int excl = base + sh[tid] - v;
        g_off[i] = excl;
        g_cursor[i] = excl;
    }
    // ---- grid barrier (all nblk blocks wave-1 resident) ----
    __threadfence();
    __syncthreads();
    if (tid == 0) {
        int t = atomicAdd(&g_barA, 1);
        if (t == nblk - 1) { __threadfence(); g_barR = 1; }
        else while (g_barR == 0) __nanosleep(40);
    }
    __syncthreads();
    // ---- fill phase ----
    for (int e = b * SCAN_BLOCK + tid; e < E; e += nblk * SCAN_BLOCK) {
        int d = g_dst[e];
        g_csr[atomicAdd(&g_cursor[d], 1)] = g_src[e];
    }
}

// ========== launch #3/#5: aggregation: gather fp32 rows, mean, emit packed Gp ==========
__global__ void k_aggr(const float* __restrict__ X, int N) {
    int warp = (blockIdx.x * blockDim.x + threadIdx.x) >> 5;
    if (warp >= N) return;
    int lane = threadIdx.x & 31;
    int beg = g_off[warp];
    int end = g_off[warp + 1];
    const int c = lane * 4;
    float4 acc = make_float4(0.f, 0.f, 0.f, 0.f);
    int i = beg;
    for (; i + 8 <= end; i += 8) {
        int s[8];
#pragma unroll
        for (int j = 0; j < 8; j++) s[j] = g_csr[i + j];
        float4 p[8];
#pragma unroll
        for (int j = 0; j < 8; j++)
            p[j] = *reinterpret_cast<const float4*>(X + (size_t)s[j] * D + c);
#pragma unroll
        for (int j = 0; j < 8; j++) {
            acc.x += p[j].x; acc.y += p[j].y; acc.z += p[j].z; acc.w += p[j].w;
        }
    }
    if (i + 4 <= end) {
        int s[4];
#pragma unroll
        for (int j = 0; j < 4; j++) s[j] = g_csr[i + j];
#pragma unroll
        for (int j = 0; j < 4; j++) {
            float4 p = *reinterpret_cast<const float4*>(X + (size_t)s[j] * D + c);
            acc.x += p.x; acc.y += p.y; acc.z += p.z; acc.w += p.w;
        }
        i += 4;
    }
    for (; i < end; i++) {
        float4 p = *reinterpret_cast<const float4*>(X + (size_t)g_csr[i] * D + c);
        acc.x += p.x; acc.y += p.y; acc.z += p.z; acc.w += p.w;
    }
    int deg = end - beg;
    float inv = 1.f / (float)(deg > 0 ? deg : 1);
    *reinterpret_cast<uint4*>(g_Gp + (size_t)warp * D + c) =
        make_uint4(packv(acc.x * inv), packv(acc.y * inv),
                   packv(acc.z * inv), packv(acc.w * inv));
}

// ====== mma.sync GEMM: block tile 256x128, warp tile 64x64, 2 K-chunks of 128 ======
#define GT 256
#define SROW 272                         // 256 B data + 16 pad
#define CHA_BYTES (256 * SROW)           // 69632  (A: 256 rows)
#define CHB_BYTES (128 * SROW)           // 34816  (B: 128 n-rows)
#define OFF_AHI 0
#define OFF_ALO (CHA_BYTES)
#define OFF_BHI (2 * CHA_BYTES)
#define OFF_BLO (2 * CHA_BYTES + CHB_BYTES)
#define SM_TOTAL (2 * CHA_BYTES + 2 * CHB_BYTES)   // 208896 B, 1 block/SM

__device__ __forceinline__ uint32_t smem_u32(const void* p) {
    uint32_t a;
    asm("{ .reg .u64 t; cvta.to.shared.u64 t, %1; cvt.u32.u64 %0, t; }" : "=r"(a) : "l"(p));
    return a;
}
__device__ __forceinline__ void ldsm_x4(uint32_t* r, uint32_t addr) {
    asm volatile("ldmatrix.sync.aligned.m8n8.x4.shared.b16 {%0,%1,%2,%3}, [%4];"
                 : "=r"(r[0]), "=r"(r[1]), "=r"(r[2]), "=r"(r[3]) : "r"(addr));
}
__device__ __forceinline__ void mma16816(float* c, const uint32_t* a, const uint32_t* b) {
    asm volatile(
        "mma.sync.aligned.m16n8k16.row.col.f32.bf16.bf16.f32 "
        "{%0,%1,%2,%3}, {%4,%5,%6,%7}, {%8,%9}, {%0,%1,%2,%3};"
        : "+f"(c[0]), "+f"(c[1]), "+f"(c[2]), "+f"(c[3])
        : "r"(a[0]), "r"(a[1]), "r"(a[2]), "r"(a[3]), "r"(b[0]), "r"(b[1]));
}

// OUTP=1: relu, write fp32 outf AND packed outp.  OUTP=0: write fp32 outf only.
template <int OUTP>
__global__ void __launch_bounds__(GT, 1)
k_mma(const uint32_t* __restrict__ Ap0, const uint32_t* __restrict__ Ap1,
      const __nv_bfloat16* __restrict__ Bhi, const __nv_bfloat16* __restrict__ Blo,
      const float* __restrict__ bias, float* __restrict__ outf,
      uint32_t* __restrict__ outp, int N)
{
    extern __shared__ char smem[];
    const uint32_t sb = smem_u32(smem);
    const int tid = threadIdx.x;
    const int wid = tid >> 5, lane = tid & 31;
    const int wm = wid >> 1, wn = wid & 1;     // 4x2 warp grid, 64x64 per warp
    const int n0 = blockIdx.x * 256;

    float acc[4][8][4];
#pragma unroll
    for (int mf = 0; mf < 4; mf++)
#pragma unroll
        for (int nf = 0; nf < 8; nf++)
#pragma unroll
            for (int q = 0; q < 4; q++) acc[mf][nf][q] = 0.f;

    // ldmatrix bases
    const uint32_t a_off = (uint32_t)(wm * 64 + (lane & 15)) * SROW + (uint32_t)(lane >> 4) * 16;
    const uint32_t b_row = (uint32_t)(wn * 64 + (lane & 7) + (((lane >> 4) & 1) << 3));
    const uint32_t b_off = b_row * SROW + (uint32_t)((lane >> 3) & 1) * 16;

#pragma unroll
    for (int chunk = 0; chunk < 2; chunk++) {
        const int kofs = chunk * 128;
        const uint32_t* Ap = chunk ? Ap1 : Ap0;
        // ---- A: one thread per row; de-interleave packed row into Ahi/Alo ----
        {
            int grow = n0 + tid;
            bool valid = grow < N;
#pragma unroll
            for (int j = 0; j < 32; j++) {
                uint4 p = valid ? *reinterpret_cast<const uint4*>(Ap + (size_t)grow * D + j * 4)
                                : make_uint4(0, 0, 0, 0);
                uint32_t h0 = __byte_perm(p.x, p.y, 0x5410);
                uint32_t h1 = __byte_perm(p.z, p.w, 0x5410);
                uint32_t l0 = __byte_perm(p.x, p.y, 0x7632);
                uint32_t l1 = __byte_perm(p.z, p.w, 0x7632);
                uint32_t so = (uint32_t)tid * SROW + (uint32_t)j * 8;
                *reinterpret_cast<uint2*>(smem + OFF_AHI + so) = make_uint2(h0, h1);
                *reinterpret_cast<uint2*>(smem + OFF_ALO + so) = make_uint2(l0, l1);
            }
        }
        // ---- B: 2 threads per n-row, k-half of [128][256] ----
        {
            int brow = tid >> 1, bseg = tid & 1;
#pragma unroll
            for (int j = 0; j < 8; j++) {
                int c16 = bseg * 8 + j;
                uint32_t so = (uint32_t)brow * SROW + (uint32_t)c16 * 16;
                size_t gb = (size_t)brow * 256 + kofs + c16 * 8;
                *reinterpret_cast<uint4*>(smem + OFF_BHI + so) = *reinterpret_cast<const uint4*>(Bhi + gb);
                *reinterpret_cast<uint4*>(smem + OFF_BLO + so) = *reinterpret_cast<const uint4*>(Blo + gb);
            }
        }
        __syncthreads();

        // ---- compute: per k16-slice: B frags once, stream A frags through mf loop ----
#pragma unroll
        for (int ks = 0; ks < 8; ks++) {
            const uint32_t kb = (uint32_t)ks * 32;
            uint32_t bh[8][2], bl[8][2];
#pragma unroll
            for (int nb = 0; nb < 4; nb++) {
                uint32_t r[4];
                ldsm_x4(r, sb + OFF_BHI + b_off + (uint32_t)nb * 16 * SROW + kb);
                bh[nb * 2][0] = r[0]; bh[nb * 2][1] = r[1];
                bh[nb * 2 + 1][0] = r[2]; bh[nb * 2 + 1][1] = r[3];
            }
#pragma unroll
            for (int nb = 0; nb < 4; nb++) {
                uint32_t r[4];
                ldsm_x4(r, sb + OFF_BLO + b_off + (uint32_t)nb * 16 * SROW + kb);
                bl[nb * 2][0] = r[0]; bl[nb * 2][1] = r[1];
                bl[nb * 2 + 1][0] = r[2]; bl[nb * 2 + 1][1] = r[3];
            }
#pragma unroll
            for (int mf = 0; mf < 4; mf++) {
                uint32_t ah[4], al[4];
                ldsm_x4(ah, sb + OFF_AHI + a_off + (uint32_t)mf * 16 * SROW + kb);
                ldsm_x4(al, sb + OFF_ALO + a_off + (uint32_t)mf * 16 * SROW + kb);
#pragma unroll
                for (int nf = 0; nf < 8; nf++)
                    mma16816(acc[mf][nf], ah, bh[nf]);
#pragma unroll
                for (int nf = 0; nf < 8; nf++)
                    mma16816(acc[mf][nf], ah, bl[nf]);
#pragma unroll
                for (int nf = 0; nf < 8; nf++)
                    mma16816(acc[mf][nf], al, bh[nf]);
            }
        }
        __syncthreads();
    }

    // ---- epilogue ----
    const int gid = lane >> 2, t4 = lane & 3;
#pragma unroll
    for (int nf = 0; nf < 8; nf++) {
        int col = wn * 64 + nf * 8 + t4 * 2;
        float b0 = __ldg(bias + col), b1 = __ldg(bias + col + 1);
#pragma unroll
        for (int mf = 0; mf < 4; mf++) {
#pragma unroll
            for (int h = 0; h < 2; h++) {
                int m = n0 + wm * 64 + mf * 16 + gid + h * 8;
                if (m < N) {
                    float ox = acc[mf][nf][2 * h + 0] + b0;
                    float oy = acc[mf][nf][2 * h + 1] + b1;
                    if (OUTP) {
                        ox = fmaxf(ox, 0.f); oy = fmaxf(oy, 0.f);
                        *reinterpret_cast<float2*>(outf + (size_t)m * D + col) =
                            make_float2(ox, oy);
                        *reinterpret_cast<uint2*>(outp + (size_t)m * D + col) =
                            make_uint2(packv(ox), packv(oy));
                    } else {
                        *reinterpret_cast<float2*>(outf + (size_t)m * D + col) =
                            make_float2(ox, oy);
                    }
                }
            }
        }
    }
}

// ================= launch =================
extern "C" void kernel_launch(void* const* d_in, const int* in_sizes, int n_in,
                              void* d_out, int out_size) {
    const int*   edge     = (const int*)d_in[0];
    const float* node_emb = (const float*)d_in[1];
    const float* w1l      = (const float*)d_in[2];
    const float* b1       = (const float*)d_in[3];
    const float* w1r      = (const float*)d_in[4];
    const float* w2l      = (const float*)d_in[5];
    const float* b2       = (const float*)d_in[6];
    const float* w2r      = (const float*)d_in[7];
    float*       out      = (float*)d_out;

    const int E = in_sizes[0] / 2;
    const int N = in_sizes[1] / D;

    cudaFuncSetAttribute(k_mma<1>, cudaFuncAttributeMaxDynamicSharedMemorySize, SM_TOTAL);
    cudaFuncSetAttribute(k_mma<0>, cudaFuncAttributeMaxDynamicSharedMemorySize, SM_TOTAL);

    float* h1ptr = nullptr;
    uint32_t *xp, *x2p, *gp;
    __nv_bfloat16 *b1hi, *b1lo, *b2hi, *b2lo;
    cudaGetSymbolAddress((void**)&h1ptr, g_h1);
    cudaGetSymbolAddress((void**)&xp,  g_Xp);
    cudaGetSymbolAddress((void**)&x2p, g_X2p);
    cudaGetSymbolAddress((void**)&gp,  g_Gp);
    cudaGetSymbolAddress((void**)&b1hi, g_B1hi);
    cudaGetSymbolAddress((void**)&b1lo, g_B1lo);
    cudaGetSymbolAddress((void**)&b2hi, g_B2hi);
    cudaGetSymbolAddress((void**)&b2lo, g_B2lo);

    const int nblk_scan = (N + SCAN_BLOCK - 1) / SCAN_BLOCK;
    const int tiles = (N + 255) / 256;
    const int aggr_blocks = (N * 32 + 255) / 256;
    const int convx_blocks = ((N * D / 4) + 255) / 256;
    const int count_blocks = (E + 255) / 256;

    // #1 prep  #2 scanfill  #3 aggr  #4 mma1(profiled)  #5 aggr  #6 mma2
    k_prep<<<128 + convx_blocks + count_blocks, 256>>>(node_emb, w1l, w1r, w2l, w2r,
                                                       edge, N, E, convx_blocks);
    k_scanfill<<<nblk_scan, SCAN_BLOCK>>>(N, E, nblk_scan);

    k_aggr<<<aggr_blocks, 256>>>(node_emb, N);
    k_mma<1><<<tiles, GT, SM_TOTAL>>>(gp, xp, b1hi, b1lo, b1, h1ptr, x2p, N);

    k_aggr<<<aggr_blocks, 256>>>(h1ptr, N);
    k_mma<0><<<tiles, GT, SM_TOTAL>>>(gp, x2p, b2hi, b2lo, b2, out, nullptr, N);
}

// round 14
// speedup vs baseline: 1.1617x; 1.1617x over previous
#include <cuda_runtime.h>
#include <cuda_bf16.h>
#include <cstdint>

#define D 128
#define MAXE 1000000
#define MAXN 100000

typedef unsigned long long u64;

// ================= scratch =================
__device__ int      g_src[MAXE];
__device__ int      g_dst[MAXE];
__device__ int      g_csr[MAXE];
__device__ int      g_cnt[MAXN];        // zero-init; re-zeroed inline in k_scanfill
__device__ int      g_off[MAXN + 1];
__device__ int      g_cursor[MAXN];
__device__ volatile int g_scanflag[128];// reset by k_prep at replay start
__device__ int      g_barA;             // arrive counter (reset by k_prep)
__device__ volatile int g_barR;         // release flag   (reset by k_prep)
__device__ float    g_h1[(size_t)MAXN * D];
__device__ uint32_t g_Xp[(size_t)MAXN * D];
__device__ uint32_t g_X2p[(size_t)MAXN * D];
__device__ uint32_t g_Gp[(size_t)MAXN * D];
__device__ __nv_bfloat16 g_B1hi[128 * 256];
__device__ __nv_bfloat16 g_B1lo[128 * 256];
__device__ __nv_bfloat16 g_B2hi[128 * 256];
__device__ __nv_bfloat16 g_B2lo[128 * 256];

// ================= packing helpers =================
__device__ __forceinline__ uint32_t packv(float v) {
    unsigned short h = __bfloat16_as_ushort(__float2bfloat16(v));
    float r = v - __uint_as_float((uint32_t)h << 16);
    unsigned short l = __bfloat16_as_ushort(__float2bfloat16(r));
    return (uint32_t)h | ((uint32_t)l << 16);
}
__device__ __forceinline__ void split_bf(float v, __nv_bfloat16& hi, __nv_bfloat16& lo) {
    hi = __float2bfloat16(v);
    lo = __float2bfloat16(v - __bfloat162float(hi));
}

// ========== launch #1: prep = weight conv + feature pack + edge convert/count + resets ====
__global__ void k_prep(const float* __restrict__ ne,
                       const float* __restrict__ w1l, const float* __restrict__ w1r,
                       const float* __restrict__ w2l, const float* __restrict__ w2r,
                       const int* __restrict__ edge, int N, int E, int convx_blocks) {
    int b = blockIdx.x, tid = threadIdx.x;
    if (b == 0) {                       // reset sync state for this replay's scanfill
        if (tid < 128) g_scanflag[tid] = 0;
        if (tid == 128) g_barA = 0;
        if (tid == 129) g_barR = 0;
    }
    if (b < 128) {
        int layer = b >> 6;
        int t = (b & 63) * 256 + tid;
        int k = t >> 7, n = t & 127;
        const float* Wl = layer ? w2l : w1l;
        const float* Wr = layer ? w2r : w1r;
        __nv_bfloat16* Bhi = layer ? g_B2hi : g_B1hi;
        __nv_bfloat16* Blo = layer ? g_B2lo : g_B1lo;
        __nv_bfloat16 h, l;
        split_bf(Wl[k * 128 + n], h, l);
        Bhi[n * 256 + k] = h; Blo[n * 256 + k] = l;
        split_bf(Wr[k * 128 + n], h, l);
        Bhi[n * 256 + 128 + k] = h; Blo[n * 256 + 128 + k] = l;
    } else if (b < 128 + convx_blocks) {
        size_t i = ((size_t)(b - 128) * 256 + tid) * 4;
        if (i < (size_t)N * D) {
            float4 v = *reinterpret_cast<const float4*>(ne + i);
            *reinterpret_cast<uint4*>(g_Xp + i) =
                make_uint4(packv(v.x), packv(v.y), packv(v.z), packv(v.w));
        }
    } else {
        int i = (b - 128 - convx_blocks) * 256 + tid;
        if (i >= E) return;
        // sampled dtype detection: int64 values < 2^31 have zero odd words
        uint32_t odd = (uint32_t)edge[1] | (uint32_t)edge[3] | (uint32_t)edge[5] |
                       (uint32_t)edge[7] | (uint32_t)edge[9] | (uint32_t)edge[11] |
                       (uint32_t)edge[13] | (uint32_t)edge[15];
        int s, d;
        if (odd == 0) { s = edge[2 * i]; d = edge[2 * E + 2 * i]; }   // int64
        else          { s = edge[i];     d = edge[E + i]; }           // int32
        g_src[i] = s; g_dst[i] = d;
        atomicAdd(&g_cnt[d], 1);
    }
}

// ========== launch #2: scan (decoupled lookback) + resident grid barrier + CSR fill ======
#define SCAN_BLOCK 1024
__global__ void k_scanfill(int N, int E, int nblk) {
    __shared__ int sh[SCAN_BLOCK];
    __shared__ int base;
    int b = blockIdx.x, tid = threadIdx.x;
    int i = b * SCAN_BLOCK + tid;
    int v = (i < N) ? g_cnt[i] : 0;
    if (i < N) g_cnt[i] = 0;                      // reset for next replay
    sh[tid] = v;
    __syncthreads();
#pragma unroll
    for (int s = 1; s < SCAN_BLOCK; s <<= 1) {
        int t = (tid >= s) ? sh[tid - s] : 0;
        __syncthreads();
        sh[tid] += t;
        __syncthreads();
    }
    if (tid == SCAN_BLOCK - 1) {
        __threadfence();
        g_scanflag[b] = sh[SCAN_BLOCK - 1] + 1;   // publish aggregate (+1 = ready)
    }
    if (tid == 0) {
        int run = 0;
        for (int bb = 0; bb < b; bb++) {
            int f;
            while ((f = g_scanflag[bb]) == 0) __nanosleep(40);
            run += f - 1;
        }
        base = run;
        if (b == nblk - 1) g_off[N] = E;
    }
    __syncthreads();
    if (i < N) {
        int excl = base + sh[tid] - v;
        g_off[i] = excl;
        g_cursor[i] = excl;
    }
    // ---- grid barrier (all nblk blocks wave-1 resident) ----
    __threadfence();
    __syncthreads();
    if (tid == 0) {
        int t = atomicAdd(&g_barA, 1);
        if (t == nblk - 1) { __threadfence(); g_barR = 1; }
        else while (g_barR == 0) __nanosleep(40);
    }
    __syncthreads();
    // ---- fill phase ----
    for (int e = b * SCAN_BLOCK + tid; e < E; e += nblk * SCAN_BLOCK) {
        int d = g_dst[e];
        g_csr[atomicAdd(&g_cursor[d], 1)] = g_src[e];
    }
}

// ========== launch #3/#5: aggregation: gather fp32 rows, mean, emit packed Gp ==========
__global__ void k_aggr(const float* __restrict__ X, int N) {
    int warp = (blockIdx.x * blockDim.x + threadIdx.x) >> 5;
    if (warp >= N) return;
    int lane = threadIdx.x & 31;
    int beg = g_off[warp];
    int end = g_off[warp + 1];
    const int c = lane * 4;
    float4 acc = make_float4(0.f, 0.f, 0.f, 0.f);
    int i = beg;
    for (; i + 8 <= end; i += 8) {
        int s[8];
#pragma unroll
        for (int j = 0; j < 8; j++) s[j] = g_csr[i + j];
        float4 p[8];
#pragma unroll
        for (int j = 0; j < 8; j++)
            p[j] = *reinterpret_cast<const float4*>(X + (size_t)s[j] * D + c);
#pragma unroll
        for (int j = 0; j < 8; j++) {
            acc.x += p[j].x; acc.y += p[j].y; acc.z += p[j].z; acc.w += p[j].w;
        }
    }
    if (i + 4 <= end) {
        int s[4];
#pragma unroll
        for (int j = 0; j < 4; j++) s[j] = g_csr[i + j];
#pragma unroll
        for (int j = 0; j < 4; j++) {
            float4 p = *reinterpret_cast<const float4*>(X + (size_t)s[j] * D + c);
            acc.x += p.x; acc.y += p.y; acc.z += p.z; acc.w += p.w;
        }
        i += 4;
    }
    for (; i < end; i++) {
        float4 p = *reinterpret_cast<const float4*>(X + (size_t)g_csr[i] * D + c);
        acc.x += p.x; acc.y += p.y; acc.z += p.z; acc.w += p.w;
    }
    int deg = end - beg;
    float inv = 1.f / (float)(deg > 0 ? deg : 1);
    *reinterpret_cast<uint4*>(g_Gp + (size_t)warp * D + c) =
        make_uint4(packv(acc.x * inv), packv(acc.y * inv),
                   packv(acc.z * inv), packv(acc.w * inv));
}

// ====== mma.sync GEMM: tile 128x128, warp 32x64, 4 K-chunks of 64, 2 blocks/SM ======
#define GT 256
#define SROW 144                         // 128 B data + 16 pad (conflict-free ldmatrix)
#define CH_BYTES (128 * SROW)            // 18432
#define OFF_AHI 0
#define OFF_ALO (CH_BYTES)
#define OFF_BHI (2 * CH_BYTES)
#define OFF_BLO (3 * CH_BYTES)
#define SM_TOTAL (4 * CH_BYTES)          // 73728 -> 2 blocks/SM (regs capped 128)

__device__ __forceinline__ uint32_t smem_u32(const void* p) {
    uint32_t a;
    asm("{ .reg .u64 t; cvta.to.shared.u64 t, %1; cvt.u32.u64 %0, t; }" : "=r"(a) : "l"(p));
    return a;
}
__device__ __forceinline__ void ldsm_x4(uint32_t* r, uint32_t addr) {
    asm volatile("ldmatrix.sync.aligned.m8n8.x4.shared.b16 {%0,%1,%2,%3}, [%4];"
                 : "=r"(r[0]), "=r"(r[1]), "=r"(r[2]), "=r"(r[3]) : "r"(addr));
}
__device__ __forceinline__ void mma16816(float* c, const uint32_t* a, const uint32_t* b) {
    asm volatile(
        "mma.sync.aligned.m16n8k16.row.col.f32.bf16.bf16.f32 "
        "{%0,%1,%2,%3}, {%4,%5,%6,%7}, {%8,%9}, {%0,%1,%2,%3};"
        : "+f"(c[0]), "+f"(c[1]), "+f"(c[2]), "+f"(c[3])
        : "r"(a[0]), "r"(a[1]), "r"(a[2]), "r"(a[3]), "r"(b[0]), "r"(b[1]));
}

// OUTP=1: relu, write fp32 outf AND packed outp.  OUTP=0: write fp32 outf only.
template <int OUTP>
__global__ void __launch_bounds__(GT, 2)
k_mma(const uint32_t* __restrict__ Ap0, const uint32_t* __restrict__ Ap1,
      const __nv_bfloat16* __restrict__ Bhi, const __nv_bfloat16* __restrict__ Blo,
      const float* __restrict__ bias, float* __restrict__ outf,
      uint32_t* __restrict__ outp, int N)
{
    extern __shared__ char smem[];
    const uint32_t sb = smem_u32(smem);
    const int tid = threadIdx.x;
    const int wid = tid >> 5, lane = tid & 31;
    const int wm = wid >> 1, wn = wid & 1;     // 4x2 warp grid, 32x64 per warp
    const int n0 = blockIdx.x * 128;

    float acc[2][8][4];
#pragma unroll
    for (int mf = 0; mf < 2; mf++)
#pragma unroll
        for (int nf = 0; nf < 8; nf++)
#pragma unroll
            for (int q = 0; q < 4; q++) acc[mf][nf][q] = 0.f;

    const int lrow = tid >> 1;           // 0..127
    const int lseg = tid & 1;
    const uint32_t a_off = (uint32_t)(wm * 32 + (lane & 15)) * SROW + (uint32_t)(lane >> 4) * 16;
    const uint32_t b_row = (uint32_t)(wn * 64 + (lane & 7) + (((lane >> 4) & 1) << 3));
    const uint32_t b_off = b_row * SROW + (uint32_t)((lane >> 3) & 1) * 16;

#pragma unroll
    for (int chunk = 0; chunk < 4; chunk++) {
        const uint32_t* Ap = (chunk < 2) ? Ap0 : Ap1;
        const int akofs = (chunk & 1) * 64;       // uint32 offset within 128-uint32 row
        // ---- A: 64 packed uint32/row -> de-interleave hi/lo ----
        {
            int grow = n0 + lrow;
            bool valid = grow < N;
#pragma unroll
            for (int j = 0; j < 8; j++) {
                int idx16 = lseg * 8 + j;          // 0..15 (16B units of this chunk)
                uint4 p = valid ? *reinterpret_cast<const uint4*>(
                                      Ap + (size_t)grow * D + akofs + idx16 * 4)
                                : make_uint4(0, 0, 0, 0);
                uint32_t h0 = __byte_perm(p.x, p.y, 0x5410);
                uint32_t h1 = __byte_perm(p.z, p.w, 0x5410);
                uint32_t l0 = __byte_perm(p.x, p.y, 0x7632);
                uint32_t l1 = __byte_perm(p.z, p.w, 0x7632);
                uint32_t so = (uint32_t)lrow * SROW + (uint32_t)idx16 * 8;
                *reinterpret_cast<uint2*>(smem + OFF_AHI + so) = make_uint2(h0, h1);
                *reinterpret_cast<uint2*>(smem + OFF_ALO + so) = make_uint2(l0, l1);
            }
        }
        // ---- B: 64 bf16/row per operand ----
#pragma unroll
        for (int j = 0; j < 4; j++) {
            int c16 = lseg * 4 + j;                // 0..7
            uint32_t so = (uint32_t)lrow * SROW + (uint32_t)c16 * 16;
            size_t gb = (size_t)lrow * 256 + chunk * 64 + c16 * 8;
            *reinterpret_cast<uint4*>(smem + OFF_BHI + so) = *reinterpret_cast<const uint4*>(Bhi + gb);
            *reinterpret_cast<uint4*>(smem + OFF_BLO + so) = *reinterpret_cast<const uint4*>(Blo + gb);
        }
        __syncthreads();

        // ---- compute: per k16-slice, term-ordered to cap live registers < 128 ----
#pragma unroll
        for (int ks = 0; ks < 4; ks++) {
            const uint32_t kb = (uint32_t)ks * 32;
            uint32_t ah[2][4];
            ldsm_x4(ah[0], sb + OFF_AHI + a_off + kb);
            ldsm_x4(ah[1], sb + OFF_AHI + a_off + 16 * SROW + kb);
            {   // term 1: Ahi . Bhi  (bh stays live for term 3)
                uint32_t bh[8][2];
#pragma unroll
                for (int nb = 0; nb < 4; nb++) {
                    uint32_t r[4];
                    ldsm_x4(r, sb + OFF_BHI + b_off + (uint32_t)nb * 16 * SROW + kb);
                    bh[nb * 2][0] = r[0]; bh[nb * 2][1] = r[1];
                    bh[nb * 2 + 1][0] = r[2]; bh[nb * 2 + 1][1] = r[3];
                }
#pragma unroll
                for (int mf = 0; mf < 2; mf++)
#pragma unroll
                    for (int nf = 0; nf < 8; nf++)
                        mma16816(acc[mf][nf], ah[mf], bh[nf]);
                // term 2: Ahi . Blo  (bl lives only inside this scope)
                {
                    uint32_t bl[8][2];
#pragma unroll
                    for (int nb = 0; nb < 4; nb++) {
                        uint32_t r[4];
                        ldsm_x4(r, sb + OFF_BLO + b_off + (uint32_t)nb * 16 * SROW + kb);
                        bl[nb * 2][0] = r[0]; bl[nb * 2][1] = r[1];
                        bl[nb * 2 + 1][0] = r[2]; bl[nb * 2 + 1][1] = r[3];
                    }
#pragma unroll
                    for (int mf = 0; mf < 2; mf++)
#pragma unroll
                        for (int nf = 0; nf < 8; nf++)
                            mma16816(acc[mf][nf], ah[mf], bl[nf]);
                }
                // term 3: Alo . Bhi  (reuse bh; al replaces ah's slot pressure)
                {
                    uint32_t al[2][4];
                    ldsm_x4(al[0], sb + OFF_ALO + a_off + kb);
                    ldsm_x4(al[1], sb + OFF_ALO + a_off + 16 * SROW + kb);
#pragma unroll
                    for (int mf = 0; mf < 2; mf++)
#pragma unroll
                        for (int nf = 0; nf < 8; nf++)
                            mma16816(acc[mf][nf], al[mf], bh[nf]);
                }
            }
        }
        __syncthreads();
    }

    const int gid = lane >> 2, t4 = lane & 3;
#pragma unroll
    for (int nf = 0; nf < 8; nf++) {
        int col = wn * 64 + nf * 8 + t4 * 2;
        float b0 = __ldg(bias + col), b1 = __ldg(bias + col + 1);
#pragma unroll
        for (int mf = 0; mf < 2; mf++) {
#pragma unroll
            for (int h = 0; h < 2; h++) {
                int m = n0 + wm * 32 + mf * 16 + gid + h * 8;
                if (m < N) {
                    float ox = acc[mf][nf][2 * h + 0] + b0;
                    float oy = acc[mf][nf][2 * h + 1] + b1;
                    if (OUTP) {
                        ox = fmaxf(ox, 0.f); oy = fmaxf(oy, 0.f);
                        *reinterpret_cast<float2*>(outf + (size_t)m * D + col) =
                            make_float2(ox, oy);
                        *reinterpret_cast<uint2*>(outp + (size_t)m * D + col) =
                            make_uint2(packv(ox), packv(oy));
                    } else {
                        *reinterpret_cast<float2*>(outf + (size_t)m * D + col) =
                            make_float2(ox, oy);
                    }
                }
            }
        }
    }
}

// ================= launch =================
extern "C" void kernel_launch(void* const* d_in, const int* in_sizes, int n_in,
                              void* d_out, int out_size) {
    const int*   edge     = (const int*)d_in[0];
    const float* node_emb = (const float*)d_in[1];
    const float* w1l      = (const float*)d_in[2];
    const float* b1       = (const float*)d_in[3];
    const float* w1r      = (const float*)d_in[4];
    const float* w2l      = (const float*)d_in[5];
    const float* b2       = (const float*)d_in[6];
    const float* w2r      = (const float*)d_in[7];
    float*       out      = (float*)d_out;

    const int E = in_sizes[0] / 2;
    const int N = in_sizes[1] / D;

    cudaFuncSetAttribute(k_mma<1>, cudaFuncAttributeMaxDynamicSharedMemorySize, SM_TOTAL);
    cudaFuncSetAttribute(k_mma<0>, cudaFuncAttributeMaxDynamicSharedMemorySize, SM_TOTAL);

    float* h1ptr = nullptr;
    uint32_t *xp, *x2p, *gp;
    __nv_bfloat16 *b1hi, *b1lo, *b2hi, *b2lo;
    cudaGetSymbolAddress((void**)&h1ptr, g_h1);
    cudaGetSymbolAddress((void**)&xp,  g_Xp);
    cudaGetSymbolAddress((void**)&x2p, g_X2p);
    cudaGetSymbolAddress((void**)&gp,  g_Gp);
    cudaGetSymbolAddress((void**)&b1hi, g_B1hi);
    cudaGetSymbolAddress((void**)&b1lo, g_B1lo);
    cudaGetSymbolAddress((void**)&b2hi, g_B2hi);
    cudaGetSymbolAddress((void**)&b2lo, g_B2lo);

    const int nblk_scan = (N + SCAN_BLOCK - 1) / SCAN_BLOCK;
    const int tiles = (N + 127) / 128;
    const int aggr_blocks = (N * 32 + 255) / 256;
    const int convx_blocks = ((N * D / 4) + 255) / 256;
    const int count_blocks = (E + 255) / 256;

    // #1 prep  #2 scanfill  #3 aggr  #4 mma1(profiled)  #5 aggr  #6 mma2
    k_prep<<<128 + convx_blocks + count_blocks, 256>>>(node_emb, w1l, w1r, w2l, w2r,
                                                       edge, N, E, convx_blocks);
    k_scanfill<<<nblk_scan, SCAN_BLOCK>>>(N, E, nblk_scan);

    k_aggr<<<aggr_blocks, 256>>>(node_emb, N);
    k_mma<1><<<tiles, GT, SM_TOTAL>>>(gp, xp, b1hi, b1lo, b1, h1ptr, x2p, N);

    k_aggr<<<aggr_blocks, 256>>>(h1ptr, N);
    k_mma<0><<<tiles, GT, SM_TOTAL>>>(gp, x2p, b2hi, b2lo, b2, out, nullptr, N);
}

// round 15
// speedup vs baseline: 1.3450x; 1.1578x over previous
#include <cuda_runtime.h>
#include <cuda_bf16.h>
#include <cstdint>

#define D 128
#define MAXE 1000000
#define MAXN 100000

typedef unsigned long long u64;

// ================= scratch =================
__device__ int      g_src[MAXE];
__device__ int      g_dst[MAXE];
__device__ int      g_csr[MAXE];
__device__ int      g_cnt[MAXN];        // zero-init; re-zeroed inline in k_scanfill
__device__ int      g_off[MAXN + 1];
__device__ int      g_cursor[MAXN];
__device__ volatile int g_scanflag[128];// reset by k_prep at replay start
__device__ int      g_barA;             // arrive counter (reset by k_prep)
__device__ volatile int g_barR;         // release flag   (reset by k_prep)
__device__ float    g_h1[(size_t)MAXN * D];
__device__ __nv_bfloat16 g_Xhi[(size_t)MAXN * D];
__device__ __nv_bfloat16 g_Xlo[(size_t)MAXN * D];
__device__ __nv_bfloat16 g_X2hi[(size_t)MAXN * D];
__device__ __nv_bfloat16 g_X2lo[(size_t)MAXN * D];
__device__ __nv_bfloat16 g_Ghi[(size_t)MAXN * D];
__device__ __nv_bfloat16 g_Glo[(size_t)MAXN * D];
__device__ __nv_bfloat16 g_B1hi[128 * 256];
__device__ __nv_bfloat16 g_B1lo[128 * 256];
__device__ __nv_bfloat16 g_B2hi[128 * 256];
__device__ __nv_bfloat16 g_B2lo[128 * 256];

// ================= helpers =================
__device__ __forceinline__ void split_bf(float v, __nv_bfloat16& hi, __nv_bfloat16& lo) {
    hi = __float2bfloat16(v);
    lo = __float2bfloat16(v - __bfloat162float(hi));
}
__device__ __forceinline__ unsigned short bfbits(__nv_bfloat16 h) {
    return __bfloat16_as_ushort(h);
}
// pack 4 floats' hi parts (or lo parts) into uint2 (4 bf16)
__device__ __forceinline__ uint2 pack4hi(float a, float b, float c, float d) {
    __nv_bfloat16 h0, h1, h2, h3, l;
    split_bf(a, h0, l); split_bf(b, h1, l); split_bf(c, h2, l); split_bf(d, h3, l);
    return make_uint2((uint32_t)bfbits(h0) | ((uint32_t)bfbits(h1) << 16),
                      (uint32_t)bfbits(h2) | ((uint32_t)bfbits(h3) << 16));
}
__device__ __forceinline__ uint2 pack4lo(float a, float b, float c, float d) {
    __nv_bfloat16 h, l0, l1, l2, l3;
    split_bf(a, h, l0); split_bf(b, h, l1); split_bf(c, h, l2); split_bf(d, h, l3);
    return make_uint2((uint32_t)bfbits(l0) | ((uint32_t)bfbits(l1) << 16),
                      (uint32_t)bfbits(l2) | ((uint32_t)bfbits(l3) << 16));
}

// ========== launch #1: prep = weight conv + feature split + edge convert/count + resets ====
__global__ void k_prep(const float* __restrict__ ne,
                       const float* __restrict__ w1l, const float* __restrict__ w1r,
                       const float* __restrict__ w2l, const float* __restrict__ w2r,
                       const int* __restrict__ edge, int N, int E, int convx_blocks) {
    int b = blockIdx.x, tid = threadIdx.x;
    if (b == 0) {
        if (tid < 128) g_scanflag[tid] = 0;
        if (tid == 128) g_barA = 0;
        if (tid == 129) g_barR = 0;
    }
    if (b < 128) {
        int layer = b >> 6;
        int t = (b & 63) * 256 + tid;
        int k = t >> 7, n = t & 127;
        const float* Wl = layer ? w2l : w1l;
        const float* Wr = layer ? w2r : w1r;
        __nv_bfloat16* Bhi = layer ? g_B2hi : g_B1hi;
        __nv_bfloat16* Blo = layer ? g_B2lo : g_B1lo;
        __nv_bfloat16 h, l;
        split_bf(Wl[k * 128 + n], h, l);
        Bhi[n * 256 + k] = h; Blo[n * 256 + k] = l;
        split_bf(Wr[k * 128 + n], h, l);
        Bhi[n * 256 + 128 + k] = h; Blo[n * 256 + 128 + k] = l;
    } else if (b < 128 + convx_blocks) {
        size_t i = ((size_t)(b - 128) * 256 + tid) * 4;
        if (i < (size_t)N * D) {
            float4 v = *reinterpret_cast<const float4*>(ne + i);
            *reinterpret_cast<uint2*>(g_Xhi + i) = pack4hi(v.x, v.y, v.z, v.w);
            *reinterpret_cast<uint2*>(g_Xlo + i) = pack4lo(v.x, v.y, v.z, v.w);
        }
    } else {
        int i = (b - 128 - convx_blocks) * 256 + tid;
        if (i >= E) return;
        // sampled dtype detection: int64 values < 2^31 have zero odd words
        uint32_t odd = (uint32_t)edge[1] | (uint32_t)edge[3] | (uint32_t)edge[5] |
                       (uint32_t)edge[7] | (uint32_t)edge[9] | (uint32_t)edge[11] |
                       (uint32_t)edge[13] | (uint32_t)edge[15];
        int s, d;
        if (odd == 0) { s = edge[2 * i]; d = edge[2 * E + 2 * i]; }   // int64
        else          { s = edge[i];     d = edge[E + i]; }           // int32
        g_src[i] = s; g_dst[i] = d;
        atomicAdd(&g_cnt[d], 1);
    }
}

// ========== launch #2: scan (decoupled lookback) + resident grid barrier + CSR fill ======
#define SCAN_BLOCK 1024
__global__ void k_scanfill(int N, int E, int nblk) {
    __shared__ int sh[SCAN_BLOCK];
    __shared__ int base;
    int b = blockIdx.x, tid = threadIdx.x;
    int i = b * SCAN_BLOCK + tid;
    int v = (i < N) ? g_cnt[i] : 0;
    if (i < N) g_cnt[i] = 0;
    sh[tid] = v;
    __syncthreads();
#pragma unroll
    for (int s = 1; s < SCAN_BLOCK; s <<= 1) {
        int t = (tid >= s) ? sh[tid - s] : 0;
        __syncthreads();
        sh[tid] += t;
        __syncthreads();
    }
    if (tid == SCAN_BLOCK - 1) {
        __threadfence();
        g_scanflag[b] = sh[SCAN_BLOCK - 1] + 1;
    }
    if (tid == 0) {
        int run = 0;
        for (int bb = 0; bb < b; bb++) {
            int f;
            while ((f = g_scanflag[bb]) == 0) __nanosleep(40);
            run += f - 1;
        }
        base = run;
        if (b == nblk - 1) g_off[N] = E;
    }
    __syncthreads();
    if (i < N) {
        int excl = base + sh[tid] - v;
        g_off[i] = excl;
        g_cursor[i] = excl;
    }
    __threadfence();
    __syncthreads();
    if (tid == 0) {
        int t = atomicAdd(&g_barA, 1);
        if (t == nblk - 1) { __threadfence(); g_barR = 1; }
        else while (g_barR == 0) __nanosleep(40);
    }
    __syncthreads();
    for (int e = b * SCAN_BLOCK + tid; e < E; e += nblk * SCAN_BLOCK) {
        int d = g_dst[e];
        g_csr[atomicAdd(&g_cursor[d], 1)] = g_src[e];
    }
}

// ========== launch #3/#5: aggregation: gather fp32 rows, mean, emit bf16 hi/lo ==========
__global__ void k_aggr(const float* __restrict__ X, int N) {
    int warp = (blockIdx.x * blockDim.x + threadIdx.x) >> 5;
    if (warp >= N) return;
    int lane = threadIdx.x & 31;
    int beg = g_off[warp];
    int end = g_off[warp + 1];
    const int c = lane * 4;
    float4 acc = make_float4(0.f, 0.f, 0.f, 0.f);
    int i = beg;
    for (; i + 8 <= end; i += 8) {
        int s[8];
#pragma unroll
        for (int j = 0; j < 8; j++) s[j] = g_csr[i + j];
        float4 p[8];
#pragma unroll
        for (int j = 0; j < 8; j++)
            p[j] = *reinterpret_cast<const float4*>(X + (size_t)s[j] * D + c);
#pragma unroll
        for (int j = 0; j < 8; j++) {
            acc.x += p[j].x; acc.y += p[j].y; acc.z += p[j].z; acc.w += p[j].w;
        }
    }
    if (i + 4 <= end) {
        int s[4];
#pragma unroll
        for (int j = 0; j < 4; j++) s[j] = g_csr[i + j];
#pragma unroll
        for (int j = 0; j < 4; j++) {
            float4 p = *reinterpret_cast<const float4*>(X + (size_t)s[j] * D + c);
            acc.x += p.x; acc.y += p.y; acc.z += p.z; acc.w += p.w;
        }
        i += 4;
    }
    for (; i < end; i++) {
        float4 p = *reinterpret_cast<const float4*>(X + (size_t)g_csr[i] * D + c);
        acc.x += p.x; acc.y += p.y; acc.z += p.z; acc.w += p.w;
    }
    int deg = end - beg;
    float inv = 1.f / (float)(deg > 0 ? deg : 1);
    acc.x *= inv; acc.y *= inv; acc.z *= inv; acc.w *= inv;
    *reinterpret_cast<uint2*>(g_Ghi + (size_t)warp * D + c) = pack4hi(acc.x, acc.y, acc.z, acc.w);
    *reinterpret_cast<uint2*>(g_Glo + (size_t)warp * D + c) = pack4lo(acc.x, acc.y, acc.z, acc.w);
}

// ====== mma.sync GEMM: tile 128x128, 8 K-chunks of 32, cp.async 2-stage pipeline ======
#define GT 256
#define SROW 80                          // 64 B data + 16 pad (conflict-free ldmatrix)
#define OP_BYTES (128 * SROW)            // 10240 per operand per stage
#define STG_BYTES (4 * OP_BYTES)         // 40960 per stage
#define OFF_AHI 0
#define OFF_ALO OP_BYTES
#define OFF_BHI (2 * OP_BYTES)
#define OFF_BLO (3 * OP_BYTES)
#define SM_TOTAL (2 * STG_BYTES)         // 81920 -> 2 blocks/SM

__device__ __forceinline__ uint32_t smem_u32(const void* p) {
    uint32_t a;
    asm("{ .reg .u64 t; cvta.to.shared.u64 t, %1; cvt.u32.u64 %0, t; }" : "=r"(a) : "l"(p));
    return a;
}
__device__ __forceinline__ void cpa16(uint32_t dst, const void* src, int fill) {
    asm volatile("cp.async.cg.shared.global [%0], [%1], 16, %2;"
                 :: "r"(dst), "l"(src), "r"(fill) : "memory");
}
#define CP_COMMIT() asm volatile("cp.async.commit_group;" ::: "memory")
template <int NN>
__device__ __forceinline__ void cp_wait() {
    asm volatile("cp.async.wait_group %0;" :: "n"(NN) : "memory");
}
__device__ __forceinline__ void ldsm_x4(uint32_t* r, uint32_t addr) {
    asm volatile("ldmatrix.sync.aligned.m8n8.x4.shared.b16 {%0,%1,%2,%3}, [%4];"
                 : "=r"(r[0]), "=r"(r[1]), "=r"(r[2]), "=r"(r[3]) : "r"(addr));
}
__device__ __forceinline__ void mma16816(float* c, const uint32_t* a, const uint32_t* b) {
    asm volatile(
        "mma.sync.aligned.m16n8k16.row.col.f32.bf16.bf16.f32 "
        "{%0,%1,%2,%3}, {%4,%5,%6,%7}, {%8,%9}, {%0,%1,%2,%3};"
        : "+f"(c[0]), "+f"(c[1]), "+f"(c[2]), "+f"(c[3])
        : "r"(a[0]), "r"(a[1]), "r"(a[2]), "r"(a[3]), "r"(b[0]), "r"(b[1]));
}

// OUTP=1: relu, write fp32 outf AND bf16 hi/lo.  OUTP=0: write fp32 outf only.
template <int OUTP>
__global__ void __launch_bounds__(GT, 2)
k_mma(const __nv_bfloat16* __restrict__ Ghi, const __nv_bfloat16* __restrict__ Glo,
      const __nv_bfloat16* __restrict__ Xhi, const __nv_bfloat16* __restrict__ Xlo,
      const __nv_bfloat16* __restrict__ Bhi, const __nv_bfloat16* __restrict__ Blo,
      const float* __restrict__ bias, float* __restrict__ outf,
      __nv_bfloat16* __restrict__ ohi, __nv_bfloat16* __restrict__ olo, int N)
{
    extern __shared__ char smem[];
    const uint32_t sb = smem_u32(smem);
    const int tid = threadIdx.x;
    const int wid = tid >> 5, lane = tid & 31;
    const int wm = wid >> 1, wn = wid & 1;     // 4x2 warp grid, 32x64 per warp
    const int n0 = blockIdx.x * 128;

    float acc[2][8][4];
#pragma unroll
    for (int mf = 0; mf < 2; mf++)
#pragma unroll
        for (int nf = 0; nf < 8; nf++)
#pragma unroll
            for (int q = 0; q < 4; q++) acc[mf][nf][q] = 0.f;

    // loader role: 2 threads per row, each 32B of the 64B chunk-row
    const int lrow = tid >> 1;
    const int lseg = tid & 1;
    const int grow = n0 + lrow;
    const int afill = (grow < N) ? 16 : 0;        // zero-fill OOB A rows
    const uint32_t ldst = (uint32_t)lrow * SROW + (uint32_t)lseg * 32;

    // ldmatrix bases (row stride SROW=80)
    const uint32_t a_off = (uint32_t)(wm * 32 + (lane & 15)) * SROW + (uint32_t)(lane >> 4) * 16;
    const uint32_t b_row = (uint32_t)(wn * 64 + (lane & 7) + (((lane >> 4) & 1) << 3));
    const uint32_t b_off = b_row * SROW + (uint32_t)((lane >> 3) & 1) * 16;

    // issue cp.async group for chunk c into stage s
    auto load_chunk = [&](int c, int s) {
        const __nv_bfloat16* ah = (c < 4) ? Ghi : Xhi;
        const __nv_bfloat16* al = (c < 4) ? Glo : Xlo;
        const int acb = (c & 3) * 32;             // A col base within 128
        const uint32_t st = sb + (uint32_t)s * STG_BYTES;
        size_t arow = (size_t)grow * D + acb + lseg * 16;
        size_t brow = (size_t)lrow * 256 + c * 32 + lseg * 16;
        cpa16(st + OFF_AHI + ldst +  0, ah + arow,     afill);
        cpa16(st + OFF_AHI + ldst + 16, ah + arow + 8, afill);
        cpa16(st + OFF_ALO + ldst +  0, al + arow,     afill);
        cpa16(st + OFF_ALO + ldst + 16, al + arow + 8, afill);
        cpa16(st + OFF_BHI + ldst +  0, Bhi + brow,     16);
        cpa16(st + OFF_BHI + ldst + 16, Bhi + brow + 8, 16);
        cpa16(st + OFF_BLO + ldst +  0, Blo + brow,     16);
        cpa16(st + OFF_BLO + ldst + 16, Blo + brow + 8, 16);
        CP_COMMIT();
    };

    load_chunk(0, 0);
    for (int c = 0; c < 8; c++) {
        const int s = c & 1;
        if (c < 7) load_chunk(c + 1, s ^ 1);
        if (c < 7) cp_wait<1>(); else cp_wait<0>();
        __syncthreads();
        const uint32_t st = sb + (uint32_t)s * STG_BYTES;
        // ---- compute chunk: 2 k16-slices, term-ordered to cap live registers ----
#pragma unroll
        for (int ks = 0; ks < 2; ks++) {
            const uint32_t kb = (uint32_t)ks * 32;
            uint32_t ah[2][4];
            ldsm_x4(ah[0], st + OFF_AHI + a_off + kb);
            ldsm_x4(ah[1], st + OFF_AHI + a_off + 16 * SROW + kb);
            {
                uint32_t bh[8][2];
#pragma unroll
                for (int nb = 0; nb < 4; nb++) {
                    uint32_t r[4];
                    ldsm_x4(r, st + OFF_BHI + b_off + (uint32_t)nb * 16 * SROW + kb);
                    bh[nb * 2][0] = r[0]; bh[nb * 2][1] = r[1];
                    bh[nb * 2 + 1][0] = r[2]; bh[nb * 2 + 1][1] = r[3];
                }
#pragma unroll
                for (int mf = 0; mf < 2; mf++)
#pragma unroll
                    for (int nf = 0; nf < 8; nf++)
                        mma16816(acc[mf][nf], ah[mf], bh[nf]);
                {
                    uint32_t bl[8][2];
#pragma unroll
                    for (int nb = 0; nb < 4; nb++) {
                        uint32_t r[4];
                        ldsm_x4(r, st + OFF_BLO + b_off + (uint32_t)nb * 16 * SROW + kb);
                        bl[nb * 2][0] = r[0]; bl[nb * 2][1] = r[1];
                        bl[nb * 2 + 1][0] = r[2]; bl[nb * 2 + 1][1] = r[3];
                    }
#pragma unroll
                    for (int mf = 0; mf < 2; mf++)
#pragma unroll
                        for (int nf = 0; nf < 8; nf++)
                            mma16816(acc[mf][nf], ah[mf], bl[nf]);
                }
                {
                    uint32_t al[2][4];
                    ldsm_x4(al[0], st + OFF_ALO + a_off + kb);
                    ldsm_x4(al[1], st + OFF_ALO + a_off + 16 * SROW + kb);
#pragma unroll
                    for (int mf = 0; mf < 2; mf++)
#pragma unroll
                        for (int nf = 0; nf < 8; nf++)
                            mma16816(acc[mf][nf], al[mf], bh[nf]);
                }
            }
        }
        __syncthreads();   // stage free for the load issued in iteration c+1
    }

    // ---- epilogue ----
    const int gid = lane >> 2, t4 = lane & 3;
#pragma unroll
    for (int nf = 0; nf < 8; nf++) {
        int col = wn * 64 + nf * 8 + t4 * 2;
        float b0 = __ldg(bias + col), b1 = __ldg(bias + col + 1);
#pragma unroll
        for (int mf = 0; mf < 2; mf++) {
#pragma unroll
            for (int h = 0; h < 2; h++) {
                int m = n0 + wm * 32 + mf * 16 + gid + h * 8;
                if (m < N) {
                    float ox = acc[mf][nf][2 * h + 0] + b0;
                    float oy = acc[mf][nf][2 * h + 1] + b1;
                    if (OUTP) {
                        ox = fmaxf(ox, 0.f); oy = fmaxf(oy, 0.f);
                        *reinterpret_cast<float2*>(outf + (size_t)m * D + col) =
                            make_float2(ox, oy);
                        __nv_bfloat16 hx, lx, hy, ly;
                        split_bf(ox, hx, lx); split_bf(oy, hy, ly);
                        *reinterpret_cast<uint32_t*>(ohi + (size_t)m * D + col) =
                            (uint32_t)bfbits(hx) | ((uint32_t)bfbits(hy) << 16);
                        *reinterpret_cast<uint32_t*>(olo + (size_t)m * D + col) =
                            (uint32_t)bfbits(lx) | ((uint32_t)bfbits(ly) << 16);
                    } else {
                        *reinterpret_cast<float2*>(outf + (size_t)m * D + col) =
                            make_float2(ox, oy);
                    }
                }
            }
        }
    }
}

// ================= launch =================
extern "C" void kernel_launch(void* const* d_in, const int* in_sizes, int n_in,
                              void* d_out, int out_size) {
    const int*   edge     = (const int*)d_in[0];
    const float* node_emb = (const float*)d_in[1];
    const float* w1l      = (const float*)d_in[2];
    const float* b1       = (const float*)d_in[3];
    const float* w1r      = (const float*)d_in[4];
    const float* w2l      = (const float*)d_in[5];
    const float* b2       = (const float*)d_in[6];
    const float* w2r      = (const float*)d_in[7];
    float*       out      = (float*)d_out;

    const int E = in_sizes[0] / 2;
    const int N = in_sizes[1] / D;

    cudaFuncSetAttribute(k_mma<1>, cudaFuncAttributeMaxDynamicSharedMemorySize, SM_TOTAL);
    cudaFuncSetAttribute(k_mma<0>, cudaFuncAttributeMaxDynamicSharedMemorySize, SM_TOTAL);

    float* h1ptr = nullptr;
    __nv_bfloat16 *xhi, *xlo, *x2hi, *x2lo, *ghi, *glo, *b1hi, *b1lo, *b2hi, *b2lo;
    cudaGetSymbolAddress((void**)&h1ptr, g_h1);
    cudaGetSymbolAddress((void**)&xhi,  g_Xhi);
    cudaGetSymbolAddress((void**)&xlo,  g_Xlo);
    cudaGetSymbolAddress((void**)&x2hi, g_X2hi);
    cudaGetSymbolAddress((void**)&x2lo, g_X2lo);
    cudaGetSymbolAddress((void**)&ghi,  g_Ghi);
    cudaGetSymbolAddress((void**)&glo,  g_Glo);
    cudaGetSymbolAddress((void**)&b1hi, g_B1hi);
    cudaGetSymbolAddress((void**)&b1lo, g_B1lo);
    cudaGetSymbolAddress((void**)&b2hi, g_B2hi);
    cudaGetSymbolAddress((void**)&b2lo, g_B2lo);

    const int nblk_scan = (N + SCAN_BLOCK - 1) / SCAN_BLOCK;
    const int tiles = (N + 127) / 128;
    const int aggr_blocks = (N * 32 + 255) / 256;
    const int convx_blocks = ((N * D / 4) + 255) / 256;
    const int count_blocks = (E + 255) / 256;

    // #1 prep  #2 scanfill  #3 aggr  #4 mma1(profiled)  #5 aggr  #6 mma2
    k_prep<<<128 + convx_blocks + count_blocks, 256>>>(node_emb, w1l, w1r, w2l, w2r,
                                                       edge, N, E, convx_blocks);
    k_scanfill<<<nblk_scan, SCAN_BLOCK>>>(N, E, nblk_scan);

    k_aggr<<<aggr_blocks, 256>>>(node_emb, N);
    k_mma<1><<<tiles, GT, SM_TOTAL>>>(ghi, glo, xhi, xlo, b1hi, b1lo, b1,
                                      h1ptr, x2hi, x2lo, N);

    k_aggr<<<aggr_blocks, 256>>>(h1ptr, N);
    k_mma<0><<<tiles, GT, SM_TOTAL>>>(ghi, glo, x2hi, x2lo, b2hi, b2lo, b2,
                                      out, nullptr, nullptr, N);
}

// round 16
// speedup vs baseline: 1.3776x; 1.0242x over previous
#include <cuda_runtime.h>
#include <cuda_bf16.h>
#include <cstdint>

#define D 128
#define MAXE 1000000
#define MAXN 100000

typedef unsigned long long u64;

// ================= scratch =================
__device__ int      g_src[MAXE];
__device__ int      g_dst[MAXE];
__device__ int      g_csr[MAXE];
__device__ int      g_cnt[MAXN];        // zero-init; re-zeroed inline in k_scanfill
__device__ int      g_off[MAXN + 1];
__device__ int      g_cursor[MAXN];
__device__ volatile int g_scanflag[128];// reset by k_prep at replay start
__device__ int      g_barA;             // arrive counter (reset by k_prep)
__device__ volatile int g_barR;         // release flag   (reset by k_prep)
__device__ float    g_h1[(size_t)MAXN * D];
__device__ __nv_bfloat16 g_Xhi[(size_t)MAXN * D];
__device__ __nv_bfloat16 g_Xlo[(size_t)MAXN * D];
__device__ __nv_bfloat16 g_X2hi[(size_t)MAXN * D];
__device__ __nv_bfloat16 g_X2lo[(size_t)MAXN * D];
__device__ __nv_bfloat16 g_Ghi[(size_t)MAXN * D];
__device__ __nv_bfloat16 g_Glo[(size_t)MAXN * D];
__device__ __nv_bfloat16 g_B1hi[128 * 256];
__device__ __nv_bfloat16 g_B1lo[128 * 256];
__device__ __nv_bfloat16 g_B2hi[128 * 256];
__device__ __nv_bfloat16 g_B2lo[128 * 256];

// ================= helpers =================
__device__ __forceinline__ void split_bf(float v, __nv_bfloat16& hi, __nv_bfloat16& lo) {
    hi = __float2bfloat16(v);
    lo = __float2bfloat16(v - __bfloat162float(hi));
}
__device__ __forceinline__ unsigned short bfbits(__nv_bfloat16 h) {
    return __bfloat16_as_ushort(h);
}
__device__ __forceinline__ uint2 pack4hi(float a, float b, float c, float d) {
    __nv_bfloat16 h0, h1, h2, h3, l;
    split_bf(a, h0, l); split_bf(b, h1, l); split_bf(c, h2, l); split_bf(d, h3, l);
    return make_uint2((uint32_t)bfbits(h0) | ((uint32_t)bfbits(h1) << 16),
                      (uint32_t)bfbits(h2) | ((uint32_t)bfbits(h3) << 16));
}
__device__ __forceinline__ uint2 pack4lo(float a, float b, float c, float d) {
    __nv_bfloat16 h, l0, l1, l2, l3;
    split_bf(a, h, l0); split_bf(b, h, l1); split_bf(c, h, l2); split_bf(d, h, l3);
    return make_uint2((uint32_t)bfbits(l0) | ((uint32_t)bfbits(l1) << 16),
                      (uint32_t)bfbits(l2) | ((uint32_t)bfbits(l3) << 16));
}

// ========== launch #1: prep = weight conv + feature split + edge convert/count + resets ====
__global__ void k_prep(const float* __restrict__ ne,
                       const float* __restrict__ w1l, const float* __restrict__ w1r,
                       const float* __restrict__ w2l, const float* __restrict__ w2r,
                       const int* __restrict__ edge, int N, int E, int convx_blocks) {
    int b = blockIdx.x, tid = threadIdx.x;
    if (b == 0) {
        if (tid < 128) g_scanflag[tid] = 0;
        if (tid == 128) g_barA = 0;
        if (tid == 129) g_barR = 0;
    }
    if (b < 128) {
        int layer = b >> 6;
        int t = (b & 63) * 256 + tid;
        int k = t >> 7, n = t & 127;
        const float* Wl = layer ? w2l : w1l;
        const float* Wr = layer ? w2r : w1r;
        __nv_bfloat16* Bhi = layer ? g_B2hi : g_B1hi;
        __nv_bfloat16* Blo = layer ? g_B2lo : g_B1lo;
        __nv_bfloat16 h, l;
        split_bf(Wl[k * 128 + n], h, l);
        Bhi[n * 256 + k] = h; Blo[n * 256 + k] = l;
        split_bf(Wr[k * 128 + n], h, l);
        Bhi[n * 256 + 128 + k] = h; Blo[n * 256 + 128 + k] = l;
    } else if (b < 128 + convx_blocks) {
        size_t i = ((size_t)(b - 128) * 256 + tid) * 4;
        if (i < (size_t)N * D) {
            float4 v = *reinterpret_cast<const float4*>(ne + i);
            *reinterpret_cast<uint2*>(g_Xhi + i) = pack4hi(v.x, v.y, v.z, v.w);
            *reinterpret_cast<uint2*>(g_Xlo + i) = pack4lo(v.x, v.y, v.z, v.w);
        }
    } else {
        int i = (b - 128 - convx_blocks) * 256 + tid;
        if (i >= E) return;
        // sampled dtype detection: int64 values < 2^31 have zero odd words
        uint32_t odd = (uint32_t)edge[1] | (uint32_t)edge[3] | (uint32_t)edge[5] |
                       (uint32_t)edge[7] | (uint32_t)edge[9] | (uint32_t)edge[11] |
                       (uint32_t)edge[13] | (uint32_t)edge[15];
        int s, d;
        if (odd == 0) { s = edge[2 * i]; d = edge[2 * E + 2 * i]; }   // int64
        else          { s = edge[i];     d = edge[E + i]; }           // int32
        g_src[i] = s; g_dst[i] = d;
        atomicAdd(&g_cnt[d], 1);
    }
}

// ========== launch #2: scan (decoupled lookback) + resident grid barrier + CSR fill ======
#define SCAN_BLOCK 1024
__global__ void k_scanfill(int N, int E, int nblk) {
    __shared__ int sh[SCAN_BLOCK];
    __shared__ int base;
    int b = blockIdx.x, tid = threadIdx.x;
    int i = b * SCAN_BLOCK + tid;
    int v = (i < N) ? g_cnt[i] : 0;
    if (i < N) g_cnt[i] = 0;
    sh[tid] = v;
    __syncthreads();
#pragma unroll
    for (int s = 1; s < SCAN_BLOCK; s <<= 1) {
        int t = (tid >= s) ? sh[tid - s] : 0;
        __syncthreads();
        sh[tid] += t;
        __syncthreads();
    }
    if (tid == SCAN_BLOCK - 1) {
        __threadfence();
        g_scanflag[b] = sh[SCAN_BLOCK - 1] + 1;
    }
    if (tid == 0) {
        int run = 0;
        for (int bb = 0; bb < b; bb++) {
            int f;
            while ((f = g_scanflag[bb]) == 0) __nanosleep(40);
            run += f - 1;
        }
        base = run;
        if (b == nblk - 1) g_off[N] = E;
    }
    __syncthreads();
    if (i < N) {
        int excl = base + sh[tid] - v;
        g_off[i] = excl;
        g_cursor[i] = excl;
    }
    __threadfence();
    __syncthreads();
    if (tid == 0) {
        int t = atomicAdd(&g_barA, 1);
        if (t == nblk - 1) { __threadfence(); g_barR = 1; }
        else while (g_barR == 0) __nanosleep(40);
    }
    __syncthreads();
    for (int e = b * SCAN_BLOCK + tid; e < E; e += nblk * SCAN_BLOCK) {
        int d = g_dst[e];
        g_csr[atomicAdd(&g_cursor[d], 1)] = g_src[e];
    }
}

// ========== launch #3/#5: aggregation: gather fp32 rows, mean, emit bf16 hi/lo ==========
__global__ void k_aggr(const float* __restrict__ X, int N) {
    int warp = (blockIdx.x * blockDim.x + threadIdx.x) >> 5;
    if (warp >= N) return;
    int lane = threadIdx.x & 31;
    int beg = g_off[warp];
    int end = g_off[warp + 1];
    const int c = lane * 4;
    float4 acc = make_float4(0.f, 0.f, 0.f, 0.f);
    int i = beg;
    for (; i + 8 <= end; i += 8) {
        int s[8];
#pragma unroll
        for (int j = 0; j < 8; j++) s[j] = g_csr[i + j];
        float4 p[8];
#pragma unroll
        for (int j = 0; j < 8; j++)
            p[j] = *reinterpret_cast<const float4*>(X + (size_t)s[j] * D + c);
#pragma unroll
        for (int j = 0; j < 8; j++) {
            acc.x += p[j].x; acc.y += p[j].y; acc.z += p[j].z; acc.w += p[j].w;
        }
    }
    if (i + 4 <= end) {
        int s[4];
#pragma unroll
        for (int j = 0; j < 4; j++) s[j] = g_csr[i + j];
#pragma unroll
        for (int j = 0; j < 4; j++) {
            float4 p = *reinterpret_cast<const float4*>(X + (size_t)s[j] * D + c);
            acc.x += p.x; acc.y += p.y; acc.z += p.z; acc.w += p.w;
        }
        i += 4;
    }
    for (; i < end; i++) {
        float4 p = *reinterpret_cast<const float4*>(X + (size_t)g_csr[i] * D + c);
        acc.x += p.x; acc.y += p.y; acc.z += p.z; acc.w += p.w;
    }
    int deg = end - beg;
    float inv = 1.f / (float)(deg > 0 ? deg : 1);
    acc.x *= inv; acc.y *= inv; acc.z *= inv; acc.w *= inv;
    *reinterpret_cast<uint2*>(g_Ghi + (size_t)warp * D + c) = pack4hi(acc.x, acc.y, acc.z, acc.w);
    *reinterpret_cast<uint2*>(g_Glo + (size_t)warp * D + c) = pack4lo(acc.x, acc.y, acc.z, acc.w);
}

// ====== mma.sync GEMM: tile 128x128, 8 K-chunks of 32, cp.async 2-stage, 1 sync/chunk ======
#define GT 256
#define SROW 80                          // 64 B data + 16 pad (conflict-free ldmatrix)
#define OP_BYTES (128 * SROW)
#define STG_BYTES (4 * OP_BYTES)         // 40960 per stage
#define OFF_AHI 0
#define OFF_ALO OP_BYTES
#define OFF_BHI (2 * OP_BYTES)
#define OFF_BLO (3 * OP_BYTES)
#define SM_TOTAL (2 * STG_BYTES)         // 81920 -> 2 blocks/SM

__device__ __forceinline__ uint32_t smem_u32(const void* p) {
    uint32_t a;
    asm("{ .reg .u64 t; cvta.to.shared.u64 t, %1; cvt.u32.u64 %0, t; }" : "=r"(a) : "l"(p));
    return a;
}
__device__ __forceinline__ void cpa16(uint32_t dst, const void* src, int fill) {
    asm volatile("cp.async.cg.shared.global [%0], [%1], 16, %2;"
                 :: "r"(dst), "l"(src), "r"(fill) : "memory");
}
#define CP_COMMIT() asm volatile("cp.async.commit_group;" ::: "memory")
template <int NN>
__device__ __forceinline__ void cp_wait() {
    asm volatile("cp.async.wait_group %0;" :: "n"(NN) : "memory");
}
__device__ __forceinline__ void ldsm_x4(uint32_t* r, uint32_t addr) {
    asm volatile("ldmatrix.sync.aligned.m8n8.x4.shared.b16 {%0,%1,%2,%3}, [%4];"
                 : "=r"(r[0]), "=r"(r[1]), "=r"(r[2]), "=r"(r[3]) : "r"(addr));
}
__device__ __forceinline__ void mma16816(float* c, const uint32_t* a, const uint32_t* b) {
    asm volatile(
        "mma.sync.aligned.m16n8k16.row.col.f32.bf16.bf16.f32 "
        "{%0,%1,%2,%3}, {%4,%5,%6,%7}, {%8,%9}, {%0,%1,%2,%3};"
        : "+f"(c[0]), "+f"(c[1]), "+f"(c[2]), "+f"(c[3])
        : "r"(a[0]), "r"(a[1]), "r"(a[2]), "r"(a[3]), "r"(b[0]), "r"(b[1]));
}

// OUTP=1: relu, write fp32 outf AND bf16 hi/lo.  OUTP=0: write fp32 outf only.
template <int OUTP>
__global__ void __launch_bounds__(GT, 2)
k_mma(const __nv_bfloat16* __restrict__ Ghi, const __nv_bfloat16* __restrict__ Glo,
      const __nv_bfloat16* __restrict__ Xhi, const __nv_bfloat16* __restrict__ Xlo,
      const __nv_bfloat16* __restrict__ Bhi, const __nv_bfloat16* __restrict__ Blo,
      const float* __restrict__ bias, float* __restrict__ outf,
      __nv_bfloat16* __restrict__ ohi, __nv_bfloat16* __restrict__ olo, int N)
{
    extern __shared__ char smem[];
    const uint32_t sb = smem_u32(smem);
    const int tid = threadIdx.x;
    const int wid = tid >> 5, lane = tid & 31;
    const int wm = wid >> 1, wn = wid & 1;     // 4x2 warp grid, 32x64 per warp
    const int n0 = blockIdx.x * 128;

    float acc[2][8][4];
#pragma unroll
    for (int mf = 0; mf < 2; mf++)
#pragma unroll
        for (int nf = 0; nf < 8; nf++)
#pragma unroll
            for (int q = 0; q < 4; q++) acc[mf][nf][q] = 0.f;

    const int lrow = tid >> 1;
    const int lseg = tid & 1;
    const int grow = n0 + lrow;
    const int afill = (grow < N) ? 16 : 0;
    const uint32_t ldst = (uint32_t)lrow * SROW + (uint32_t)lseg * 32;

    const uint32_t a_off = (uint32_t)(wm * 32 + (lane & 15)) * SROW + (uint32_t)(lane >> 4) * 16;
    const uint32_t b_row = (uint32_t)(wn * 64 + (lane & 7) + (((lane >> 4) & 1) << 3));
    const uint32_t b_off = b_row * SROW + (uint32_t)((lane >> 3) & 1) * 16;

    auto load_chunk = [&](int c, int s) {
        const __nv_bfloat16* ah = (c < 4) ? Ghi : Xhi;
        const __nv_bfloat16* al = (c < 4) ? Glo : Xlo;
        const int acb = (c & 3) * 32;
        const uint32_t st = sb + (uint32_t)s * STG_BYTES;
        size_t arow = (size_t)grow * D + acb + lseg * 16;
        size_t brow = (size_t)lrow * 256 + c * 32 + lseg * 16;
        cpa16(st + OFF_AHI + ldst +  0, ah + arow,     afill);
        cpa16(st + OFF_AHI + ldst + 16, ah + arow + 8, afill);
        cpa16(st + OFF_ALO + ldst +  0, al + arow,     afill);
        cpa16(st + OFF_ALO + ldst + 16, al + arow + 8, afill);
        cpa16(st + OFF_BHI + ldst +  0, Bhi + brow,     16);
        cpa16(st + OFF_BHI + ldst + 16, Bhi + brow + 8, 16);
        cpa16(st + OFF_BLO + ldst +  0, Blo + brow,     16);
        cpa16(st + OFF_BLO + ldst + 16, Blo + brow + 8, 16);
        CP_COMMIT();
    };

    load_chunk(0, 0);
    for (int c = 0; c < 8; c++) {
        const int s = c & 1;
        cp_wait<0>();          // chunk c complete (issued last iteration, fully overlapped)
        __syncthreads();       // (a) chunk c visible to all; (b) stage s^1 free to overwrite
        if (c < 7) load_chunk(c + 1, s ^ 1);   // overlaps compute below
        const uint32_t st = sb + (uint32_t)s * STG_BYTES;
#pragma unroll
        for (int ks = 0; ks < 2; ks++) {
            const uint32_t kb = (uint32_t)ks * 32;
            // front-load ah, bh, bl fragments; al streams in during bh-MMA batch
            uint32_t ah[2][4];
            ldsm_x4(ah[0], st + OFF_AHI + a_off + kb);
            ldsm_x4(ah[1], st + OFF_AHI + a_off + 16 * SROW + kb);
            uint32_t bh[8][2], bl[8][2];
#pragma unroll
            for (int nb = 0; nb < 4; nb++) {
                uint32_t r[4];
                ldsm_x4(r, st + OFF_BHI + b_off + (uint32_t)nb * 16 * SROW + kb);
                bh[nb * 2][0] = r[0]; bh[nb * 2][1] = r[1];
                bh[nb * 2 + 1][0] = r[2]; bh[nb * 2 + 1][1] = r[3];
            }
#pragma unroll
            for (int nb = 0; nb < 4; nb++) {
                uint32_t r[4];
                ldsm_x4(r, st + OFF_BLO + b_off + (uint32_t)nb * 16 * SROW + kb);
                bl[nb * 2][0] = r[0]; bl[nb * 2][1] = r[1];
                bl[nb * 2 + 1][0] = r[2]; bl[nb * 2 + 1][1] = r[3];
            }
            // term 1: Ahi.Bhi (hides al's ldsm below via MMA pipeline)
#pragma unroll
            for (int mf = 0; mf < 2; mf++)
#pragma unroll
                for (int nf = 0; nf < 8; nf++)
                    mma16816(acc[mf][nf], ah[mf], bh[nf]);
            uint32_t al[2][4];
            ldsm_x4(al[0], st + OFF_ALO + a_off + kb);
            ldsm_x4(al[1], st + OFF_ALO + a_off + 16 * SROW + kb);
            // term 2: Ahi.Blo
#pragma unroll
            for (int mf = 0; mf < 2; mf++)
#pragma unroll
                for (int nf = 0; nf < 8; nf++)
                    mma16816(acc[mf][nf], ah[mf], bl[nf]);
            // term 3: Alo.Bhi
#pragma unroll
            for (int mf = 0; mf < 2; mf++)
#pragma unroll
                for (int nf = 0; nf < 8; nf++)
                    mma16816(acc[mf][nf], al[mf], bh[nf]);
        }
    }

    // ---- epilogue ----
    const int gid = lane >> 2, t4 = lane & 3;
#pragma unroll
    for (int nf = 0; nf < 8; nf++) {
        int col = wn * 64 + nf * 8 + t4 * 2;
        float b0 = __ldg(bias + col), b1 = __ldg(bias + col + 1);
#pragma unroll
        for (int mf = 0; mf < 2; mf++) {
#pragma unroll
            for (int h = 0; h < 2; h++) {
                int m = n0 + wm * 32 + mf * 16 + gid + h * 8;
                if (m < N) {
                    float ox = acc[mf][nf][2 * h + 0] + b0;
                    float oy = acc[mf][nf][2 * h + 1] + b1;
                    if (OUTP) {
                        ox = fmaxf(ox, 0.f); oy = fmaxf(oy, 0.f);
                        *reinterpret_cast<float2*>(outf + (size_t)m * D + col) =
                            make_float2(ox, oy);
                        __nv_bfloat16 hx, lx, hy, ly;
                        split_bf(ox, hx, lx); split_bf(oy, hy, ly);
                        *reinterpret_cast<uint32_t*>(ohi + (size_t)m * D + col) =
                            (uint32_t)bfbits(hx) | ((uint32_t)bfbits(hy) << 16);
                        *reinterpret_cast<uint32_t*>(olo + (size_t)m * D + col) =
                            (uint32_t)bfbits(lx) | ((uint32_t)bfbits(ly) << 16);
                    } else {
                        *reinterpret_cast<float2*>(outf + (size_t)m * D + col) =
                            make_float2(ox, oy);
                    }
                }
            }
        }
    }
}

// ================= launch =================
extern "C" void kernel_launch(void* const* d_in, const int* in_sizes, int n_in,
                              void* d_out, int out_size) {
    const int*   edge     = (const int*)d_in[0];
    const float* node_emb = (const float*)d_in[1];
    const float* w1l      = (const float*)d_in[2];
    const float* b1       = (const float*)d_in[3];
    const float* w1r      = (const float*)d_in[4];
    const float* w2l      = (const float*)d_in[5];
    const float* b2       = (const float*)d_in[6];
    const float* w2r      = (const float*)d_in[7];
    float*       out      = (float*)d_out;

    const int E = in_sizes[0] / 2;
    const int N = in_sizes[1] / D;

    cudaFuncSetAttribute(k_mma<1>, cudaFuncAttributeMaxDynamicSharedMemorySize, SM_TOTAL);
    cudaFuncSetAttribute(k_mma<0>, cudaFuncAttributeMaxDynamicSharedMemorySize, SM_TOTAL);

    float* h1ptr = nullptr;
    __nv_bfloat16 *xhi, *xlo, *x2hi, *x2lo, *ghi, *glo, *b1hi, *b1lo, *b2hi, *b2lo;
    cudaGetSymbolAddress((void**)&h1ptr, g_h1);
    cudaGetSymbolAddress((void**)&xhi,  g_Xhi);
    cudaGetSymbolAddress((void**)&xlo,  g_Xlo);
    cudaGetSymbolAddress((void**)&x2hi, g_X2hi);
    cudaGetSymbolAddress((void**)&x2lo, g_X2lo);
    cudaGetSymbolAddress((void**)&ghi,  g_Ghi);
    cudaGetSymbolAddress((void**)&glo,  g_Glo);
    cudaGetSymbolAddress((void**)&b1hi, g_B1hi);
    cudaGetSymbolAddress((void**)&b1lo, g_B1lo);
    cudaGetSymbolAddress((void**)&b2hi, g_B2hi);
    cudaGetSymbolAddress((void**)&b2lo, g_B2lo);

    const int nblk_scan = (N + SCAN_BLOCK - 1) / SCAN_BLOCK;
    const int tiles = (N + 127) / 128;
    const int aggr_blocks = (N * 32 + 255) / 256;
    const int convx_blocks = ((N * D / 4) + 255) / 256;
    const int count_blocks = (E + 255) / 256;

    // #1 prep  #2 scanfill  #3 aggr  #4 mma1(profiled)  #5 aggr  #6 mma2
    k_prep<<<128 + convx_blocks + count_blocks, 256>>>(node_emb, w1l, w1r, w2l, w2r,
                                                       edge, N, E, convx_blocks);
    k_scanfill<<<nblk_scan, SCAN_BLOCK>>>(N, E, nblk_scan);

    k_aggr<<<aggr_blocks, 256>>>(node_emb, N);
    k_mma<1><<<tiles, GT, SM_TOTAL>>>(ghi, glo, xhi, xlo, b1hi, b1lo, b1,
                                      h1ptr, x2hi, x2lo, N);

    k_aggr<<<aggr_blocks, 256>>>(h1ptr, N);
    k_mma<0><<<tiles, GT, SM_TOTAL>>>(ghi, glo, x2hi, x2lo, b2hi, b2lo, b2,
                                      out, nullptr, nullptr, N);
}